// round 10
// baseline (speedup 1.0000x reference)
#include <cuda_runtime.h>
#include <math.h>

#define NSEG 1024
#define NPIX (512 * 512)
#define NCH  21
#define NB   4
#define HB   128           // K1 x-blocks per batch (512 blocks total = 1 wave)
#define QX   128           // quad x-blocks per batch
#define K3_TOTAL (QX * NB)

// Persistent accumulators: start zero (static init), and K3's last block
// re-zeroes them after use, so every graph replay sees clean state.
__device__ float  g_msum[NB * NSEG];
__device__ float  g_mcnt[NB * NSEG];
__device__ double g_w2[NB];
__device__ double g_quad[NB];
__device__ unsigned int g_done;

// ---------------------------------------------------------------------------
// K1: grid (HB, NB) x 512 — 512 identical blocks, exactly one wave.
// Each block: shared-mem histogram over 2048 px + 2048-float4 slice of ||W||^2.
// Flush: global float atomics into g_msum/g_mcnt (skip empty bins),
// double atomic into g_w2[b].
// ---------------------------------------------------------------------------
__global__ __launch_bounds__(512) void k1(const float* __restrict__ pred,
                                          const void* __restrict__ ids_v,
                                          const float* __restrict__ W) {
    __shared__ float s_sum[NSEG];
    __shared__ int   s_cnt[NSEG];
    __shared__ int   s_nonzero;
    __shared__ float red[16];

    const int tid = threadIdx.x;
    const int b   = blockIdx.y;
    const int x   = blockIdx.x;

    if (tid == 0) s_nonzero = 0;
    for (int i = tid; i < NSEG; i += 512) { s_sum[i] = 0.f; s_cnt[i] = 0; }
    __syncthreads();

    // dtype probe: int64 ids in [0,1024) -> all odd 32-bit words zero (L2-hot).
    if (tid < 128 && ((const unsigned int*)ids_v)[2 * tid + 1] != 0u)
        atomicOr(&s_nonzero, 1);
    __syncthreads();
    const int is64 = !s_nonzero;

    // ---- histogram phase ----
    const float4* __restrict__ p4 =
        (const float4*)(pred + (size_t)b * NCH * NPIX);
    const int4* __restrict__ id32v =
        (const int4*)((const int*)ids_v + (size_t)b * NPIX);
    const longlong2* __restrict__ id64v =
        (const longlong2*)((const long long*)ids_v + (size_t)b * NPIX);

    const int q = x * 512 + tid;                     // one float4-group/thread
    float4 acc = make_float4(0.f, 0.f, 0.f, 0.f);
    #pragma unroll
    for (int c = 0; c < NCH; ++c) {
        float4 v = p4[(size_t)c * (NPIX / 4) + q];
        acc.x += v.x; acc.y += v.y; acc.z += v.z; acc.w += v.w;
    }
    int i0, i1, i2, i3;
    if (is64) {
        longlong2 a = id64v[2 * q];
        longlong2 c = id64v[2 * q + 1];
        i0 = (int)a.x; i1 = (int)a.y; i2 = (int)c.x; i3 = (int)c.y;
    } else {
        int4 iv = id32v[q];
        i0 = iv.x; i1 = iv.y; i2 = iv.z; i3 = iv.w;
    }
    atomicAdd(&s_sum[i0 & (NSEG - 1)], acc.x); atomicAdd(&s_cnt[i0 & (NSEG - 1)], 1);
    atomicAdd(&s_sum[i1 & (NSEG - 1)], acc.y); atomicAdd(&s_cnt[i1 & (NSEG - 1)], 1);
    atomicAdd(&s_sum[i2 & (NSEG - 1)], acc.z); atomicAdd(&s_cnt[i2 & (NSEG - 1)], 1);
    atomicAdd(&s_sum[i3 & (NSEG - 1)], acc.w); atomicAdd(&s_cnt[i3 & (NSEG - 1)], 1);

    // ---- W^2 phase (overlaps hist atomic latency across warps) ----
    const float4* __restrict__ Wb = (const float4*)(W + (size_t)b * NSEG * NSEG);
    float ws = 0.f;
    #pragma unroll
    for (int j = 0; j < 4; ++j) {
        float4 v = Wb[x * 2048 + j * 512 + tid];
        ws += v.x * v.x + v.y * v.y + v.z * v.z + v.w * v.w;
    }
    #pragma unroll
    for (int o = 16; o > 0; o >>= 1)
        ws += __shfl_xor_sync(0xffffffffu, ws, o);
    if ((tid & 31) == 0) red[tid >> 5] = ws;

    __syncthreads();

    // ---- flush: global atomics (skip empty bins, ~13.5%) ----
    for (int i = tid; i < NSEG; i += 512) {
        int c = s_cnt[i];
        if (c != 0) {
            atomicAdd(&g_msum[b * NSEG + i], s_sum[i]);
            atomicAdd(&g_mcnt[b * NSEG + i], (float)c);
        }
    }
    if (tid == 0) {
        double t = 0.0;
        #pragma unroll
        for (int w = 0; w < 16; ++w) t += (double)red[w];
        atomicAdd(&g_w2[b], t);
    }
}

// ---------------------------------------------------------------------------
// K3: quad[b] = m^T L m ; last block computes loss and RESETS all state.
// grid (QX, NB) x 256 (8 warps -> 8 rows each).
// ---------------------------------------------------------------------------
__global__ __launch_bounds__(256) void k3(const float* __restrict__ L,
                                          float* __restrict__ out) {
    __shared__ float s_m[NSEG];
    const int b    = blockIdx.y;
    const int tid  = threadIdx.x;
    const int warp = tid >> 5;
    const int lane = tid & 31;

    for (int i = tid; i < NSEG; i += 256) {
        float c = g_mcnt[b * NSEG + i];
        s_m[i] = (c > 0.f) ? g_msum[b * NSEG + i] / c : 0.f;
    }
    __syncthreads();

    const int r = blockIdx.x * 8 + warp;
    const float4* __restrict__ Lr =
        (const float4*)(L + (size_t)b * NSEG * NSEG + (size_t)r * NSEG);
    const float4* __restrict__ sm4 = (const float4*)s_m;

    float s = 0.f;
    #pragma unroll
    for (int i = 0; i < NSEG / 128; ++i) {            // 8 float4 iters
        int c4 = i * 32 + lane;
        float4 l4 = Lr[c4];
        float4 m4 = sm4[c4];
        s += l4.x * m4.x + l4.y * m4.y + l4.z * m4.z + l4.w * m4.w;
    }
    #pragma unroll
    for (int o = 16; o > 0; o >>= 1)
        s += __shfl_xor_sync(0xffffffffu, s, o);
    if (lane == 0)
        atomicAdd(&g_quad[b], (double)s * (double)s_m[r]);

    __syncthreads();
    __shared__ int s_last;
    if (tid == 0) {
        __threadfence();
        unsigned int prev = atomicAdd(&g_done, 1u);
        s_last = (prev == K3_TOTAL - 1);
    }
    __syncthreads();

    if (s_last) {
        // all other blocks have flushed quad and finished reading g_msum/g_mcnt
        if (tid == 0) {
            __threadfence();
            double loss = 0.0;
            #pragma unroll
            for (int k = 0; k < NB; ++k)
                loss += (2.0 / sqrt(g_w2[k])) * ((double)NCH * g_quad[k]);
            out[0] = (float)loss;
            __threadfence();
            // reset scalar state for the next graph replay
            #pragma unroll
            for (int k = 0; k < NB; ++k) { g_quad[k] = 0.0; g_w2[k] = 0.0; }
            g_done = 0u;
        }
        // reset histogram accumulators for the next graph replay
        for (int i = tid; i < NB * NSEG; i += 256) {
            g_msum[i] = 0.f;
            g_mcnt[i] = 0.f;
        }
    }
}

extern "C" void kernel_launch(void* const* d_in, const int* in_sizes, int n_in,
                              void* d_out, int out_size) {
    const float* pred = (const float*)d_in[0];
    const float* W    = (const float*)d_in[1];
    const float* L    = (const float*)d_in[2];
    const void*  ids  = (const void*)d_in[3];
    float* out = (float*)d_out;

    k1<<<dim3(HB, NB), 512>>>(pred, ids, W);
    k3<<<dim3(QX, NB), 256>>>(L, out);
}

// round 11
// speedup vs baseline: 1.1440x; 1.1440x over previous
#include <cuda_runtime.h>
#include <math.h>

#define NSEG 1024
#define NPIX (512 * 512)
#define NCH  21
#define NB   4
#define HB   128           // K1 x-blocks per batch (512 blocks total = 1 wave)
#define QX   128           // quad x-blocks per batch
#define K3_TOTAL (QX * NB)

// Persistent accumulators: start zero (static init), and K3's last block
// re-zeroes them after use, so every graph replay sees clean state.
__device__ float  g_msum[NB * NSEG];
__device__ float  g_mcnt[NB * NSEG];
__device__ double g_w2[NB];
__device__ double g_quad[NB];
__device__ unsigned int g_done;

// ---------------------------------------------------------------------------
// K1: grid (HB, NB) x 512 — 512 identical blocks, exactly one wave.
// Each block: shared-mem histogram over 2048 px + 2048-float4 slice of ||W||^2.
// Flush: global float atomics into g_msum/g_mcnt (skip empty bins),
// one double atomic into g_w2[b] per block.
// ---------------------------------------------------------------------------
__global__ __launch_bounds__(512) void k1(const float* __restrict__ pred,
                                          const void* __restrict__ ids_v,
                                          const float* __restrict__ W) {
    __shared__ float s_sum[NSEG];
    __shared__ int   s_cnt[NSEG];
    __shared__ int   s_nonzero;
    __shared__ float red[16];

    const int tid = threadIdx.x;
    const int b   = blockIdx.y;
    const int x   = blockIdx.x;

    if (tid == 0) s_nonzero = 0;
    for (int i = tid; i < NSEG; i += 512) { s_sum[i] = 0.f; s_cnt[i] = 0; }
    __syncthreads();

    // dtype probe: int64 ids in [0,1024) -> all odd 32-bit words zero (L2-hot).
    if (tid < 128 && ((const unsigned int*)ids_v)[2 * tid + 1] != 0u)
        atomicOr(&s_nonzero, 1);
    __syncthreads();
    const int is64 = !s_nonzero;

    // ---- histogram phase ----
    const float4* __restrict__ p4 =
        (const float4*)(pred + (size_t)b * NCH * NPIX);
    const int4* __restrict__ id32v =
        (const int4*)((const int*)ids_v + (size_t)b * NPIX);
    const longlong2* __restrict__ id64v =
        (const longlong2*)((const long long*)ids_v + (size_t)b * NPIX);

    const int q = x * 512 + tid;                     // one float4-group/thread
    float4 acc = make_float4(0.f, 0.f, 0.f, 0.f);
    #pragma unroll
    for (int c = 0; c < NCH; ++c) {
        float4 v = p4[(size_t)c * (NPIX / 4) + q];
        acc.x += v.x; acc.y += v.y; acc.z += v.z; acc.w += v.w;
    }
    int i0, i1, i2, i3;
    if (is64) {
        longlong2 a = id64v[2 * q];
        longlong2 c = id64v[2 * q + 1];
        i0 = (int)a.x; i1 = (int)a.y; i2 = (int)c.x; i3 = (int)c.y;
    } else {
        int4 iv = id32v[q];
        i0 = iv.x; i1 = iv.y; i2 = iv.z; i3 = iv.w;
    }
    atomicAdd(&s_sum[i0 & (NSEG - 1)], acc.x); atomicAdd(&s_cnt[i0 & (NSEG - 1)], 1);
    atomicAdd(&s_sum[i1 & (NSEG - 1)], acc.y); atomicAdd(&s_cnt[i1 & (NSEG - 1)], 1);
    atomicAdd(&s_sum[i2 & (NSEG - 1)], acc.z); atomicAdd(&s_cnt[i2 & (NSEG - 1)], 1);
    atomicAdd(&s_sum[i3 & (NSEG - 1)], acc.w); atomicAdd(&s_cnt[i3 & (NSEG - 1)], 1);

    // ---- W^2 phase (overlaps hist atomic latency across warps) ----
    const float4* __restrict__ Wb = (const float4*)(W + (size_t)b * NSEG * NSEG);
    float ws = 0.f;
    #pragma unroll
    for (int j = 0; j < 4; ++j) {
        float4 v = Wb[x * 2048 + j * 512 + tid];
        ws += v.x * v.x + v.y * v.y + v.z * v.z + v.w * v.w;
    }
    #pragma unroll
    for (int o = 16; o > 0; o >>= 1)
        ws += __shfl_xor_sync(0xffffffffu, ws, o);
    if ((tid & 31) == 0) red[tid >> 5] = ws;

    __syncthreads();

    // ---- flush: global atomics (skip empty bins) ----
    for (int i = tid; i < NSEG; i += 512) {
        int c = s_cnt[i];
        if (c != 0) {
            atomicAdd(&g_msum[b * NSEG + i], s_sum[i]);
            atomicAdd(&g_mcnt[b * NSEG + i], (float)c);
        }
    }
    if (tid == 0) {
        double t = 0.0;
        #pragma unroll
        for (int w = 0; w < 16; ++w) t += (double)red[w];
        atomicAdd(&g_w2[b], t);
    }
}

// ---------------------------------------------------------------------------
// K3: quad[b] = m^T L m. 8 warps -> 8 rows; per-block double reduction ->
// ONE atomicAdd per block (512 total over 4 addresses, vs 4096 before).
// Last block computes loss and resets all persistent state.
// ---------------------------------------------------------------------------
__global__ __launch_bounds__(256) void k3(const float* __restrict__ L,
                                          float* __restrict__ out) {
    __shared__ float  s_m[NSEG];
    __shared__ double qred[8];
    __shared__ int    s_last;

    const int b    = blockIdx.y;
    const int tid  = threadIdx.x;
    const int warp = tid >> 5;
    const int lane = tid & 31;

    for (int i = tid; i < NSEG; i += 256) {
        float c = g_mcnt[b * NSEG + i];
        s_m[i] = (c > 0.f) ? g_msum[b * NSEG + i] / c : 0.f;
    }
    __syncthreads();

    const int r = blockIdx.x * 8 + warp;
    const float4* __restrict__ Lr =
        (const float4*)(L + (size_t)b * NSEG * NSEG + (size_t)r * NSEG);
    const float4* __restrict__ sm4 = (const float4*)s_m;

    float s = 0.f;
    #pragma unroll
    for (int i = 0; i < NSEG / 128; ++i) {            // 8 float4 iters
        int c4 = i * 32 + lane;
        float4 l4 = Lr[c4];
        float4 m4 = sm4[c4];
        s += l4.x * m4.x + l4.y * m4.y + l4.z * m4.z + l4.w * m4.w;
    }
    #pragma unroll
    for (int o = 16; o > 0; o >>= 1)
        s += __shfl_xor_sync(0xffffffffu, s, o);
    if (lane == 0)
        qred[warp] = (double)s * (double)s_m[r];
    __syncthreads();

    if (tid == 0) {
        double t = 0.0;
        #pragma unroll
        for (int w = 0; w < 8; ++w) t += qred[w];
        atomicAdd(&g_quad[b], t);

        __threadfence();
        unsigned int prev = atomicAdd(&g_done, 1u);
        s_last = (prev == K3_TOTAL - 1);
    }
    __syncthreads();

    if (s_last) {
        if (tid == 0) {
            __threadfence();
            double loss = 0.0;
            #pragma unroll
            for (int k = 0; k < NB; ++k)
                loss += (2.0 / sqrt(g_w2[k])) * ((double)NCH * g_quad[k]);
            out[0] = (float)loss;
            __threadfence();
            #pragma unroll
            for (int k = 0; k < NB; ++k) { g_quad[k] = 0.0; g_w2[k] = 0.0; }
            g_done = 0u;
        }
        for (int i = tid; i < NB * NSEG; i += 256) {
            g_msum[i] = 0.f;
            g_mcnt[i] = 0.f;
        }
    }
}

extern "C" void kernel_launch(void* const* d_in, const int* in_sizes, int n_in,
                              void* d_out, int out_size) {
    const float* pred = (const float*)d_in[0];
    const float* W    = (const float*)d_in[1];
    const float* L    = (const float*)d_in[2];
    const void*  ids  = (const void*)d_in[3];
    float* out = (float*)d_out;

    k1<<<dim3(HB, NB), 512>>>(pred, ids, W);
    k3<<<dim3(QX, NB), 256>>>(L, out);
}

// round 12
// speedup vs baseline: 1.1502x; 1.0054x over previous
#include <cuda_runtime.h>
#include <math.h>

#define NSEG 1024
#define NPIX (512 * 512)
#define NCH  21
#define NB   4
#define HB   128           // K1 x-blocks per batch (512 blocks total = 1 wave)
#define QX   256           // quad x-blocks per batch (1024 blocks, 4 rows each)
#define K3_TOTAL (QX * NB)

// Persistent accumulators: start zero (static init); K3's last block re-zeroes
// the atomically-accumulated ones after use (graph-replay safe).
__device__ float  g_msum[NB * NSEG];
__device__ float  g_mcnt[NB * NSEG];
__device__ double g_w2[NB];
__device__ double g_quadp[NB * QX];          // per-block partials — overwritten
__device__ unsigned int g_done;

// ---------------------------------------------------------------------------
// K1: grid (HB, NB) x 512 — 512 identical blocks, exactly one wave.
// Shared-mem histogram over 2048 px + 2048-float4 slice of ||W||^2.
// Flush: global float atomics (skip empty bins) + one double atomic for w2.
// ---------------------------------------------------------------------------
__global__ __launch_bounds__(512) void k1(const float* __restrict__ pred,
                                          const void* __restrict__ ids_v,
                                          const float* __restrict__ W) {
    __shared__ float s_sum[NSEG];
    __shared__ int   s_cnt[NSEG];
    __shared__ int   s_nonzero;
    __shared__ float red[16];

    const int tid = threadIdx.x;
    const int b   = blockIdx.y;
    const int x   = blockIdx.x;

    if (tid == 0) s_nonzero = 0;
    for (int i = tid; i < NSEG; i += 512) { s_sum[i] = 0.f; s_cnt[i] = 0; }
    __syncthreads();

    // dtype probe: int64 ids in [0,1024) -> all odd 32-bit words zero (L2-hot).
    if (tid < 128 && ((const unsigned int*)ids_v)[2 * tid + 1] != 0u)
        atomicOr(&s_nonzero, 1);
    __syncthreads();
    const int is64 = !s_nonzero;

    // ---- histogram phase ----
    const float4* __restrict__ p4 =
        (const float4*)(pred + (size_t)b * NCH * NPIX);
    const int4* __restrict__ id32v =
        (const int4*)((const int*)ids_v + (size_t)b * NPIX);
    const longlong2* __restrict__ id64v =
        (const longlong2*)((const long long*)ids_v + (size_t)b * NPIX);

    const int q = x * 512 + tid;                     // one float4-group/thread
    float4 acc = make_float4(0.f, 0.f, 0.f, 0.f);
    #pragma unroll
    for (int c = 0; c < NCH; ++c) {
        float4 v = p4[(size_t)c * (NPIX / 4) + q];
        acc.x += v.x; acc.y += v.y; acc.z += v.z; acc.w += v.w;
    }
    int i0, i1, i2, i3;
    if (is64) {
        longlong2 a = id64v[2 * q];
        longlong2 c = id64v[2 * q + 1];
        i0 = (int)a.x; i1 = (int)a.y; i2 = (int)c.x; i3 = (int)c.y;
    } else {
        int4 iv = id32v[q];
        i0 = iv.x; i1 = iv.y; i2 = iv.z; i3 = iv.w;
    }
    atomicAdd(&s_sum[i0 & (NSEG - 1)], acc.x); atomicAdd(&s_cnt[i0 & (NSEG - 1)], 1);
    atomicAdd(&s_sum[i1 & (NSEG - 1)], acc.y); atomicAdd(&s_cnt[i1 & (NSEG - 1)], 1);
    atomicAdd(&s_sum[i2 & (NSEG - 1)], acc.z); atomicAdd(&s_cnt[i2 & (NSEG - 1)], 1);
    atomicAdd(&s_sum[i3 & (NSEG - 1)], acc.w); atomicAdd(&s_cnt[i3 & (NSEG - 1)], 1);

    // ---- W^2 phase ----
    const float4* __restrict__ Wb = (const float4*)(W + (size_t)b * NSEG * NSEG);
    float ws = 0.f;
    #pragma unroll
    for (int j = 0; j < 4; ++j) {
        float4 v = Wb[x * 2048 + j * 512 + tid];
        ws += v.x * v.x + v.y * v.y + v.z * v.z + v.w * v.w;
    }
    #pragma unroll
    for (int o = 16; o > 0; o >>= 1)
        ws += __shfl_xor_sync(0xffffffffu, ws, o);
    if ((tid & 31) == 0) red[tid >> 5] = ws;

    __syncthreads();

    // ---- flush ----
    for (int i = tid; i < NSEG; i += 512) {
        int c = s_cnt[i];
        if (c != 0) {
            atomicAdd(&g_msum[b * NSEG + i], s_sum[i]);
            atomicAdd(&g_mcnt[b * NSEG + i], (float)c);
        }
    }
    if (tid == 0) {
        double t = 0.0;
        #pragma unroll
        for (int w = 0; w < 16; ++w) t += (double)red[w];
        atomicAdd(&g_w2[b], t);
    }
}

// ---------------------------------------------------------------------------
// K3: quad[b] = m^T L m. grid (QX, NB) x 256. 4 rows/block, 2 warps/row
// (2KB per warp, 4 float4 iters). Block partial -> g_quadp slot (overwrite,
// no atomic). Last block (counter) reduces slots, writes loss, resets state.
// ---------------------------------------------------------------------------
__global__ __launch_bounds__(256) void k3(const float* __restrict__ L,
                                          float* __restrict__ out) {
    __shared__ float  s_m[NSEG];
    __shared__ double qred[8];
    __shared__ int    s_last;

    const int b    = blockIdx.y;
    const int x    = blockIdx.x;
    const int tid  = threadIdx.x;
    const int warp = tid >> 5;
    const int lane = tid & 31;

    for (int i = tid; i < NSEG; i += 256) {
        float c = g_mcnt[b * NSEG + i];
        s_m[i] = (c > 0.f) ? g_msum[b * NSEG + i] / c : 0.f;
    }
    __syncthreads();

    const int r    = x * 4 + (warp >> 1);            // row for this warp
    const int half = warp & 1;                       // which half of the row
    const float4* __restrict__ Lr =
        (const float4*)(L + (size_t)b * NSEG * NSEG + (size_t)r * NSEG);
    const float4* __restrict__ sm4 = (const float4*)s_m;

    float s = 0.f;
    #pragma unroll
    for (int i = 0; i < 4; ++i) {                    // 4 float4 iters = 2KB
        int c4 = half * 128 + i * 32 + lane;
        float4 l4 = Lr[c4];
        float4 m4 = sm4[c4];
        s += l4.x * m4.x + l4.y * m4.y + l4.z * m4.z + l4.w * m4.w;
    }
    #pragma unroll
    for (int o = 16; o > 0; o >>= 1)
        s += __shfl_xor_sync(0xffffffffu, s, o);
    if (lane == 0)
        qred[warp] = (double)s;
    __syncthreads();

    if (tid == 0) {
        double t = 0.0;
        #pragma unroll
        for (int k = 0; k < 4; ++k)
            t += (qred[2 * k] + qred[2 * k + 1]) * (double)s_m[x * 4 + k];
        g_quadp[b * QX + x] = t;                     // overwrite, no atomic

        __threadfence();
        unsigned int prev = atomicAdd(&g_done, 1u);
        s_last = (prev == K3_TOTAL - 1);
    }
    __syncthreads();

    if (s_last) {
        // warps 0..NB-1 reduce each batch's QX partials
        if (warp < NB) {
            double t = 0.0;
            #pragma unroll
            for (int j = 0; j < QX / 32; ++j)        // 8 loads
                t += g_quadp[warp * QX + j * 32 + lane];
            #pragma unroll
            for (int o = 16; o > 0; o >>= 1)
                t += __shfl_xor_sync(0xffffffffu, t, o);
            if (lane == 0) qred[warp] = t;
        }
        __syncthreads();
        if (tid == 0) {
            double loss = 0.0;
            #pragma unroll
            for (int k = 0; k < NB; ++k)
                loss += (2.0 / sqrt(g_w2[k])) * ((double)NCH * qred[k]);
            out[0] = (float)loss;
            __threadfence();
            #pragma unroll
            for (int k = 0; k < NB; ++k) g_w2[k] = 0.0;
            g_done = 0u;
        }
        // reset histogram accumulators for the next graph replay
        for (int i = tid; i < NB * NSEG; i += 256) {
            g_msum[i] = 0.f;
            g_mcnt[i] = 0.f;
        }
    }
}

extern "C" void kernel_launch(void* const* d_in, const int* in_sizes, int n_in,
                              void* d_out, int out_size) {
    const float* pred = (const float*)d_in[0];
    const float* W    = (const float*)d_in[1];
    const float* L    = (const float*)d_in[2];
    const void*  ids  = (const void*)d_in[3];
    float* out = (float*)d_out;

    k1<<<dim3(HB, NB), 512>>>(pred, ids, W);
    k3<<<dim3(QX, NB), 256>>>(L, out);
}